// round 1
// baseline (speedup 1.0000x reference)
#include <cuda_runtime.h>
#include <cuda_bf16.h>
#include <stdint.h>

// CRF log-likelihood: B=128, S=1024, T=256.
// Strategy: per-batch forward recursion in the *linear* domain:
//   p'_j ∝ (Σ_i p_i * E_ij) * exp(emit_j),  E = exp(transitions) (constant, bf16 in smem)
// with per-step max renormalization tracked in C (log scale).
// One CTA per batch (128 CTAs), 256 threads (one per tag j).

#define CRF_B 128
#define CRF_S 1024
#define CRF_T 256
#define NTH   256
#define NCHUNK 32  // 256 i-values / 8 per chunk

// smem: E (32*256 uint4 = 131072 B) + p double buffer (2*256 f32) + red (32 f32)
#define SMEM_BYTES (131072 + 2048 + 128)

__device__ __forceinline__ float warp_max(float v) {
#pragma unroll
    for (int o = 16; o > 0; o >>= 1)
        v = fmaxf(v, __shfl_xor_sync(0xffffffffu, v, o));
    return v;
}
__device__ __forceinline__ float warp_sum(float v) {
#pragma unroll
    for (int o = 16; o > 0; o >>= 1)
        v += __shfl_xor_sync(0xffffffffu, v, o);
    return v;
}

__global__ void crf_zero(float* out) {
    if (threadIdx.x == 0 && blockIdx.x == 0) out[0] = 0.0f;
}

__global__ void __launch_bounds__(NTH, 1) crf_forward_kernel(
    const float* __restrict__ logits,   // (B, S, T) f32
    const int*   __restrict__ tags,     // (B, S) i32
    const float* __restrict__ trans,    // (T, T) f32
    const float* __restrict__ start_t,  // (T,) f32
    const float* __restrict__ end_t,    // (T,) f32
    float* __restrict__ out)            // scalar
{
    extern __shared__ unsigned char sm[];
    uint4* Es   = reinterpret_cast<uint4*>(sm);           // [NCHUNK][256] : E bf16, 8 i's interleaved
    float* pbuf = reinterpret_cast<float*>(sm + 131072);  // [2][256]
    float* red  = pbuf + 512;                             // [8] (+pad)

    const int b    = blockIdx.x;
    const int j    = threadIdx.x;
    const int wid  = j >> 5;
    const int lane = j & 31;
    const float* lg = logits + (size_t)b * (CRF_S * CRF_T);

    // ---- Build E = exp(trans) as bf16, interleaved 8-deep along i ----
    for (int idx = j; idx < CRF_T * CRF_T; idx += NTH) {
        int i  = idx >> 8;
        int jj = idx & 255;
        float e = __expf(trans[idx]);
        __nv_bfloat16 h = __float2bfloat16(e);
        reinterpret_cast<__nv_bfloat16*>(&Es[(i >> 3) * CRF_T + jj])[i & 7] = h;
    }

    // ---- t = 0 init ----
    float u = start_t[j] + lg[j];
    float wm = warp_max(u);
    if (lane == 0) red[wid] = wm;
    __syncthreads();  // also covers E-fill completion
    float m = red[0];
#pragma unroll
    for (int w = 1; w < 8; ++w) m = fmaxf(m, red[w]);
    float C = m;

    float* pc = pbuf;        // current p
    float* pn = pbuf + 256;  // next p
    pc[j] = __expf(u - m);
    __syncthreads();

    float e_next = lg[CRF_T + j];   // prefetch emit for t=1
    const float endv = end_t[j];

    // ---- forward scan over steps 1..S-1 ----
    for (int t = 1; t < CRF_S; ++t) {
        float emit = e_next;
        if (t + 1 < CRF_S) e_next = lg[(size_t)(t + 1) * CRF_T + j];

        float a0 = 0.f, a1 = 0.f, a2 = 0.f, a3 = 0.f;
        const float4* p4 = reinterpret_cast<const float4*>(pc);
#pragma unroll
        for (int c = 0; c < NCHUNK; ++c) {
            uint4 ew  = Es[c * CRF_T + j];   // E[8c..8c+7][j], bf16 pairs
            float4 pa = p4[2 * c];           // p[8c..8c+3]  (warp-broadcast)
            float4 pb = p4[2 * c + 1];       // p[8c+4..8c+7]
            a0 = fmaf(pa.x, __int_as_float(ew.x << 16),          a0);
            a1 = fmaf(pa.y, __int_as_float(ew.x & 0xffff0000u),  a1);
            a2 = fmaf(pa.z, __int_as_float(ew.y << 16),          a2);
            a3 = fmaf(pa.w, __int_as_float(ew.y & 0xffff0000u),  a3);
            a0 = fmaf(pb.x, __int_as_float(ew.z << 16),          a0);
            a1 = fmaf(pb.y, __int_as_float(ew.z & 0xffff0000u),  a1);
            a2 = fmaf(pb.z, __int_as_float(ew.w << 16),          a2);
            a3 = fmaf(pb.w, __int_as_float(ew.w & 0xffff0000u),  a3);
        }
        float acc = (a0 + a1) + (a2 + a3);       // Σ_i p_i * E_ij  (>= E_min > 0)
        float uu  = __logf(acc) + emit;          // log-domain value (minus C)

        float wmx = warp_max(uu);
        if (lane == 0) red[wid] = wmx;
        __syncthreads();
        float mm = red[0];
#pragma unroll
        for (int w = 1; w < 8; ++w) mm = fmaxf(mm, red[w]);
        C += mm;
        pn[j] = __expf(uu - mm);                 // renormalized p (max = 1)
        __syncthreads();
        float* tmp = pc; pc = pn; pn = tmp;
    }

    // ---- logZ = C + log Σ_j p_j * exp(end_j) ----
    float term = pc[j] * __expf(endv);
    float ws = warp_sum(term);
    if (lane == 0) red[wid] = ws;
    __syncthreads();
    float ssum = 0.f;
#pragma unroll
    for (int w = 0; w < 8; ++w) ssum += red[w];
    float logZ = C + __logf(ssum);

    // ---- joint score (numerator); mask is all-ones in this problem ----
    __syncthreads();  // protect red reuse
    const int* tg = tags + b * CRF_S;
    float num = 0.f;
    for (int t = j; t < CRF_S; t += NTH) {
        int tt = tg[t];
        num += lg[(size_t)t * CRF_T + tt];
        if (t + 1 < CRF_S) num += trans[tt * CRF_T + tg[t + 1]];
    }
    if (j == 0) num += start_t[tg[0]] + end_t[tg[CRF_S - 1]];
    float wsn = warp_sum(num);
    if (lane == 0) red[wid] = wsn;
    __syncthreads();
    if (j == 0) {
        float tot = 0.f;
#pragma unroll
        for (int w = 0; w < 8; ++w) tot += red[w];
        atomicAdd(out, tot - logZ);
    }
}

extern "C" void kernel_launch(void* const* d_in, const int* in_sizes, int n_in,
                              void* d_out, int out_size)
{
    const float* logits = (const float*)d_in[0];
    const int*   tags   = (const int*)  d_in[1];
    // d_in[2] = mask: all ones per problem setup (unused)
    const float* trans  = (const float*)d_in[3];
    const float* st     = (const float*)d_in[4];
    const float* en     = (const float*)d_in[5];
    float* out = (float*)d_out;

    cudaFuncSetAttribute(crf_forward_kernel,
                         cudaFuncAttributeMaxDynamicSharedMemorySize, SMEM_BYTES);

    crf_zero<<<1, 32>>>(out);
    crf_forward_kernel<<<CRF_B, NTH, SMEM_BYTES>>>(logits, tags, trans, st, en, out);
}

// round 2
// speedup vs baseline: 3.0578x; 3.0578x over previous
#include <cuda_runtime.h>
#include <cuda_bf16.h>
#include <stdint.h>

// CRF log-likelihood: B=128, S=1024, T=256.
// Linear-domain forward recursion, one CTA per batch, thread j owns column j.
//   acc_j = sum_i p_i * E_ij   via HFMA2 (E column held in REGISTERS as bf16x2)
//   uu_j  = log(acc_j) + emit_j
// Lagged renormalization: p stored as bf16 with scale m_hat derived from the
// PREVIOUS step's block max (no reduce->broadcast on the critical path,
// exactly one __syncthreads per step). C accumulates m_hat -> exact logZ.

#define CRF_B 128
#define CRF_S 1024
#define CRF_T 256
#define NTH   256

__device__ __forceinline__ float warp_max(float v) {
#pragma unroll
    for (int o = 16; o > 0; o >>= 1)
        v = fmaxf(v, __shfl_xor_sync(0xffffffffu, v, o));
    return v;
}
__device__ __forceinline__ float warp_sum(float v) {
#pragma unroll
    for (int o = 16; o > 0; o >>= 1)
        v += __shfl_xor_sync(0xffffffffu, v, o);
    return v;
}
__device__ __forceinline__ float max8(const float* r) {
    float4 a = *reinterpret_cast<const float4*>(r);
    float4 b = *reinterpret_cast<const float4*>(r + 4);
    return fmaxf(fmaxf(fmaxf(a.x, a.y), fmaxf(a.z, a.w)),
                 fmaxf(fmaxf(b.x, b.y), fmaxf(b.z, b.w)));
}

__global__ void crf_zero(float* out) {
    if (threadIdx.x == 0 && blockIdx.x == 0) out[0] = 0.0f;
}

__global__ void __launch_bounds__(NTH, 1) crf_forward_kernel(
    const float* __restrict__ logits,   // (B, S, T) f32
    const int*   __restrict__ tags,     // (B, S) i32
    const float* __restrict__ trans,    // (T, T) f32
    const float* __restrict__ start_t,  // (T,) f32
    const float* __restrict__ end_t,    // (T,) f32
    float* __restrict__ out)            // scalar
{
    __shared__ __align__(16) __nv_bfloat16 pbuf[2][CRF_T];
    __shared__ __align__(16) float red[2][8];

    const int b    = blockIdx.x;
    const int j    = threadIdx.x;
    const int wid  = j >> 5;
    const int lane = j & 31;
    const float* lg = logits + (size_t)b * (CRF_S * CRF_T);

    // ---- E column j in registers: ereg[i] = (E[2i][j], E[2i+1][j]) bf16x2 ----
    __nv_bfloat162 ereg[128];
#pragma unroll
    for (int i = 0; i < 128; ++i) {
        float e0 = __expf(trans[(2 * i)     * CRF_T + j]);
        float e1 = __expf(trans[(2 * i + 1) * CRF_T + j]);
        ereg[i] = __floats2bfloat162_rn(e0, e1);
    }

    // ---- t = 0 init ----
    float u = start_t[j] + lg[j];
    float wm = warp_max(u);
    if (lane == 0) red[0][wid] = wm;
    __syncthreads();
    float m0 = max8(red[0]);          // exact block max of uu_0 = u
    float C = m0, m_hat_prev = m0;
    pbuf[0][j] = __float2bfloat16(__expf(u - m0));
    __syncthreads();                   // red[0] already holds warp-maxes of uu_0

    int cur = 0;
    float e_next  = lg[(size_t)1 * CRF_T + j];
    float e_next2 = lg[(size_t)2 * CRF_T + j];
    const float endv = end_t[j];

    // ---- forward scan, steps 1..S-1 ----
    for (int t = 1; t < CRF_S; ++t) {
        float emit = e_next;
        e_next = e_next2;
        if (t + 2 < CRF_S) e_next2 = lg[(size_t)(t + 2) * CRF_T + j];

        const uint4* p4 = reinterpret_cast<const uint4*>(pbuf[cur]);
        __nv_bfloat162 z = __floats2bfloat162_rn(0.f, 0.f);
        __nv_bfloat162 a0 = z, a1 = z, a2 = z, a3 = z;
#pragma unroll
        for (int c = 0; c < 32; ++c) {
            uint4 pw = p4[c];          // p[8c..8c+7] as 4 bf16x2 (warp-broadcast)
            a0 = __hfma2(*reinterpret_cast<__nv_bfloat162*>(&pw.x), ereg[4 * c + 0], a0);
            a1 = __hfma2(*reinterpret_cast<__nv_bfloat162*>(&pw.y), ereg[4 * c + 1], a1);
            a2 = __hfma2(*reinterpret_cast<__nv_bfloat162*>(&pw.z), ereg[4 * c + 2], a2);
            a3 = __hfma2(*reinterpret_cast<__nv_bfloat162*>(&pw.w), ereg[4 * c + 3], a3);
        }
        float2 f0 = __bfloat1622float2(a0);
        float2 f1 = __bfloat1622float2(a1);
        float2 f2 = __bfloat1622float2(a2);
        float2 f3 = __bfloat1622float2(a3);
        float acc = ((f0.x + f0.y) + (f1.x + f1.y)) + ((f2.x + f2.y) + (f3.x + f3.y));
        float uu = __logf(acc) + emit;         // = u_t - M_{t-1}

        // lagged normalizer: m_hat_t ≈ max_j uu_t, from previous step's block max
        float mprev = max8(red[cur]);           // = max_j uu_{t-1}
        float m_hat = mprev - m_hat_prev + 6.5f;
        C += m_hat;
        pbuf[cur ^ 1][j] = __float2bfloat16(__expf(uu - m_hat));

        float wmx = warp_max(uu);
        if (lane == 0) red[cur ^ 1][wid] = wmx;
        __syncthreads();
        m_hat_prev = m_hat;
        cur ^= 1;
    }

    // ---- logZ = C + log Σ_j p_j * exp(end_j) ----
    float pj = __bfloat162float(pbuf[cur][j]);
    float term = pj * __expf(endv);
    float ws = warp_sum(term);
    __syncthreads();
    if (lane == 0) red[0][wid] = ws;
    __syncthreads();
    float ssum = 0.f;
#pragma unroll
    for (int w = 0; w < 8; ++w) ssum += red[0][w];
    float logZ = C + __logf(ssum);

    // ---- joint score (numerator); mask is all-ones for this problem ----
    const int* tg = tags + b * CRF_S;
    float num = 0.f;
    for (int t = j; t < CRF_S; t += NTH) {
        int tt = tg[t];
        num += lg[(size_t)t * CRF_T + tt];
        if (t + 1 < CRF_S) num += trans[tt * CRF_T + tg[t + 1]];
    }
    if (j == 0) num += start_t[tg[0]] + end_t[tg[CRF_S - 1]];
    float wsn = warp_sum(num);
    __syncthreads();
    if (lane == 0) red[1][wid] = wsn;
    __syncthreads();
    if (j == 0) {
        float tot = 0.f;
#pragma unroll
        for (int w = 0; w < 8; ++w) tot += red[1][w];
        atomicAdd(out, tot - logZ);
    }
}

extern "C" void kernel_launch(void* const* d_in, const int* in_sizes, int n_in,
                              void* d_out, int out_size)
{
    const float* logits = (const float*)d_in[0];
    const int*   tags   = (const int*)  d_in[1];
    // d_in[2] = mask: all ones per problem setup (unused)
    const float* trans  = (const float*)d_in[3];
    const float* st     = (const float*)d_in[4];
    const float* en     = (const float*)d_in[5];
    float* out = (float*)d_out;

    crf_zero<<<1, 32>>>(out);
    crf_forward_kernel<<<CRF_B, NTH>>>(logits, tags, trans, st, en, out);
}

// round 3
// speedup vs baseline: 3.0607x; 1.0009x over previous
#include <cuda_runtime.h>
#include <cuda_bf16.h>
#include <stdint.h>

// CRF log-likelihood: B=128, S=1024, T=256.
// Linear-domain forward recursion, one CTA per batch, 512 threads.
// Warp layout: lanes 0-15 and 16-31 both cover j = wid*16 + (lane&15);
// lane-half 0 sums i in [0,128), half 1 sums i in [128,256). Partials are
// combined with one shfl_xor(16). Normalizer m_hat tracks thread-0's uu
// (lagged, +8 slack) -> no block max; C accumulates m_hat so logZ is exact.

#define CRF_B 128
#define CRF_S 1024
#define CRF_T 256
#define NTH   512

__device__ __forceinline__ float warp_sum(float v) {
#pragma unroll
    for (int o = 16; o > 0; o >>= 1)
        v += __shfl_xor_sync(0xffffffffu, v, o);
    return v;
}

__global__ void crf_zero(float* out) {
    if (threadIdx.x == 0 && blockIdx.x == 0) out[0] = 0.0f;
}

__global__ void __launch_bounds__(NTH, 1) crf_forward_kernel(
    const float* __restrict__ logits,   // (B, S, T) f32
    const int*   __restrict__ tags,     // (B, S) i32
    const float* __restrict__ trans,    // (T, T) f32
    const float* __restrict__ start_t,  // (T,) f32
    const float* __restrict__ end_t,    // (T,) f32
    float* __restrict__ out)            // scalar
{
    __shared__ __align__(16) __nv_bfloat16 pbuf[2][CRF_T];
    __shared__ float sbuf[2];        // uu of j=0, double-buffered
    __shared__ float red[2][16];

    const int tid  = threadIdx.x;
    const int wid  = tid >> 5;
    const int lane = tid & 31;
    const int jcol = (wid << 4) + (lane & 15);
    const int half = lane >> 4;          // 0: i in [0,128), 1: [128,256)
    const int b    = blockIdx.x;
    const float* lg = logits + (size_t)b * (CRF_S * CRF_T);

    // ---- E half-column in registers: ereg[k] = (E[ib+2k][j], E[ib+2k+1][j]) ----
    const int ib = half << 7;
    __nv_bfloat162 ereg[64];
#pragma unroll
    for (int k = 0; k < 64; ++k) {
        float e0 = __expf(trans[(ib + 2 * k)     * CRF_T + jcol]);
        float e1 = __expf(trans[(ib + 2 * k + 1) * CRF_T + jcol]);
        ereg[k] = __floats2bfloat162_rn(e0, e1);
    }
    const float endv = end_t[jcol];

    // ---- t = 0: p = exp(u), m_hat_0 = 0, C = 0 ----
    float u = start_t[jcol] + lg[jcol];
    if (lane < 16) pbuf[0][jcol] = __float2bfloat16(__expf(u));
    if (tid == 0) sbuf[0] = u;
    __syncthreads();

    float C = 0.f, m_hat_prev = 0.f;
    int cur = 0;
    float e_next  = lg[(size_t)1 * CRF_T + jcol];
    float e_next2 = lg[(size_t)2 * CRF_T + jcol];
    const int pbase = half << 4;         // uint4 index of this half's p chunk
    float val = 0.f;                     // p value for (jcol), last step

    // ---- forward scan, steps 1..S-1 ----
    for (int t = 1; t < CRF_S; ++t) {
        float s_prev = sbuf[cur];        // uu_0 of step t-1 (broadcast LDS)
        float emit = e_next;
        e_next = e_next2;
        if (t + 2 < CRF_S) e_next2 = lg[(size_t)(t + 2) * CRF_T + jcol];

        const uint4* p4 = reinterpret_cast<const uint4*>(pbuf[cur]);
        __nv_bfloat162 z = __floats2bfloat162_rn(0.f, 0.f);
        __nv_bfloat162 a0 = z, a1 = z, a2 = z, a3 = z;
#pragma unroll
        for (int c = 0; c < 16; ++c) {
            uint4 pw = p4[pbase + c];    // p[ib+8c .. ib+8c+7] as 4 bf16x2
            a0 = __hfma2(*reinterpret_cast<__nv_bfloat162*>(&pw.x), ereg[4 * c + 0], a0);
            a1 = __hfma2(*reinterpret_cast<__nv_bfloat162*>(&pw.y), ereg[4 * c + 1], a1);
            a2 = __hfma2(*reinterpret_cast<__nv_bfloat162*>(&pw.z), ereg[4 * c + 2], a2);
            a3 = __hfma2(*reinterpret_cast<__nv_bfloat162*>(&pw.w), ereg[4 * c + 3], a3);
        }
        float2 f0 = __bfloat1622float2(a0);
        float2 f1 = __bfloat1622float2(a1);
        float2 f2 = __bfloat1622float2(a2);
        float2 f3 = __bfloat1622float2(a3);
        float part = ((f0.x + f0.y) + (f1.x + f1.y)) + ((f2.x + f2.y) + (f3.x + f3.y));
        float acc = part + __shfl_xor_sync(0xffffffffu, part, 16);

        float uu = __logf(acc) + emit;               // = u_t - C_t (shifted)
        float m_hat = s_prev - m_hat_prev + 8.0f;    // lagged normalizer
        C += m_hat;
        val = __expf(uu - m_hat);
        if (lane < 16) pbuf[cur ^ 1][jcol] = __float2bfloat16(val);
        if (tid == 0) sbuf[cur ^ 1] = uu;
        __syncthreads();
        m_hat_prev = m_hat;
        cur ^= 1;
    }

    // ---- logZ = C + log sum_j p_j * exp(end_j)  (lanes<16 contribute) ----
    float term = (lane < 16) ? val * __expf(endv) : 0.f;
    float ws = warp_sum(term);
    if (lane == 0) red[0][wid] = ws;

    // ---- joint score (numerator); mask is all-ones for this problem ----
    const int* tg = tags + b * CRF_S;
    float num = 0.f;
    for (int t = tid; t < CRF_S; t += NTH) {
        int tt = tg[t];
        num += lg[(size_t)t * CRF_T + tt];
        if (t + 1 < CRF_S) num += trans[tt * CRF_T + tg[t + 1]];
    }
    if (tid == 0) num += start_t[tg[0]] + end_t[tg[CRF_S - 1]];
    float wsn = warp_sum(num);
    if (lane == 0) red[1][wid] = wsn;
    __syncthreads();

    if (tid == 0) {
        float ssum = 0.f, tot = 0.f;
#pragma unroll
        for (int w = 0; w < 16; ++w) { ssum += red[0][w]; tot += red[1][w]; }
        float logZ = C + __logf(ssum);
        atomicAdd(out, tot - logZ);
    }
}

extern "C" void kernel_launch(void* const* d_in, const int* in_sizes, int n_in,
                              void* d_out, int out_size)
{
    const float* logits = (const float*)d_in[0];
    const int*   tags   = (const int*)  d_in[1];
    // d_in[2] = mask: all ones per problem setup (unused)
    const float* trans  = (const float*)d_in[3];
    const float* st     = (const float*)d_in[4];
    const float* en     = (const float*)d_in[5];
    float* out = (float*)d_out;

    crf_zero<<<1, 32>>>(out);
    crf_forward_kernel<<<CRF_B, NTH>>>(logits, tags, trans, st, en, out);
}

// round 4
// speedup vs baseline: 3.3015x; 1.0787x over previous
#include <cuda_runtime.h>
#include <cuda_bf16.h>
#include <stdint.h>

// CRF log-likelihood: B=128, S=1024, T=256.
// Linear-domain forward recursion, one CTA per batch, 512 threads.
// Lanes 0-15 / 16-31 of each warp cover the same 16 j-columns; half 0 sums
// i in [0,128), half 1 sums i in [128,256); combined by one shfl_xor(16).
// NO log/exp on the per-step critical path:
//   q_t,j = (sum_i q_{t-1,i} E_ij) * exp(emit_t,j) / q_{t-1,0}
// exp(emit) is computed at prefetch time; the divide uses the previous step's
// broadcast scalar (both off the dependency chain). Thread 0 accumulates
// CC += log(q_t,0) so logZ is exact.

#define CRF_B 128
#define CRF_S 1024
#define CRF_T 256
#define NTH   512

__device__ __forceinline__ float warp_sum(float v) {
#pragma unroll
    for (int o = 16; o > 0; o >>= 1)
        v += __shfl_xor_sync(0xffffffffu, v, o);
    return v;
}

__global__ void crf_zero(float* out) {
    if (threadIdx.x == 0 && blockIdx.x == 0) out[0] = 0.0f;
}

__global__ void __launch_bounds__(NTH, 1) crf_forward_kernel(
    const float* __restrict__ logits,   // (B, S, T) f32
    const int*   __restrict__ tags,     // (B, S) i32
    const float* __restrict__ trans,    // (T, T) f32
    const float* __restrict__ start_t,  // (T,) f32
    const float* __restrict__ end_t,    // (T,) f32
    float* __restrict__ out)            // scalar
{
    __shared__ __align__(16) __nv_bfloat16 pbuf[2][CRF_T];
    __shared__ float sbuf[2];        // q_{t,0} (thread 0's value), double-buffered
    __shared__ float red[2][16];

    const int tid  = threadIdx.x;
    const int wid  = tid >> 5;
    const int lane = tid & 31;
    const int jcol = (wid << 4) + (lane & 15);
    const int half = lane >> 4;          // 0: i in [0,128), 1: [128,256)
    const int b    = blockIdx.x;
    const float* lg = logits + (size_t)b * (CRF_S * CRF_T);

    // ---- E half-column in registers: ereg[k] = (E[ib+2k][j], E[ib+2k+1][j]) ----
    const int ib = half << 7;
    __nv_bfloat162 ereg[64];
#pragma unroll
    for (int k = 0; k < 64; ++k) {
        float e0 = __expf(trans[(ib + 2 * k)     * CRF_T + jcol]);
        float e1 = __expf(trans[(ib + 2 * k + 1) * CRF_T + jcol]);
        ereg[k] = __floats2bfloat162_rn(e0, e1);
    }
    const float endv = end_t[jcol];

    // ---- t = 0: q_0 = exp(u_0);  CC = u_{0,0} (thread 0) ----
    float u = start_t[jcol] + lg[jcol];
    float val = __expf(u);
    if (lane < 16) pbuf[0][jcol] = __float2bfloat16(val);
    if (tid == 0) sbuf[0] = val;
    float CC = u;                        // meaningful on thread 0 only
    __syncthreads();

    int cur = 0;
    // emit/exp prefetch pipeline: W_cur = exp(emit_t) ready one step ahead
    float e_raw = lg[(size_t)2 * CRF_T + jcol];        // emit for t = 2
    float W_cur = __expf(lg[(size_t)1 * CRF_T + jcol]); // exp(emit) for t = 1
    const int pbase = half << 4;         // uint4 index of this half's p chunk

    // ---- forward scan, steps 1..S-1 ----
    for (int t = 1; t < CRF_S; ++t) {
        float s_prev = sbuf[cur];                  // broadcast LDS (off-path)
        float Wi = __fdividef(W_cur, s_prev);      // off-path (done ~cy 50)
        float W_next = __expf(e_raw);              // exp(emit_{t+1}), off-path
        if (t + 2 < CRF_S) e_raw = lg[(size_t)(t + 2) * CRF_T + jcol];

        const uint4* p4 = reinterpret_cast<const uint4*>(pbuf[cur]);
        __nv_bfloat162 z = __floats2bfloat162_rn(0.f, 0.f);
        __nv_bfloat162 a0 = z, a1 = z, a2 = z, a3 = z;
#pragma unroll
        for (int c = 0; c < 16; ++c) {
            uint4 pw = p4[pbase + c];    // q[ib+8c .. ib+8c+7] as 4 bf16x2
            a0 = __hfma2(*reinterpret_cast<__nv_bfloat162*>(&pw.x), ereg[4 * c + 0], a0);
            a1 = __hfma2(*reinterpret_cast<__nv_bfloat162*>(&pw.y), ereg[4 * c + 1], a1);
            a2 = __hfma2(*reinterpret_cast<__nv_bfloat162*>(&pw.z), ereg[4 * c + 2], a2);
            a3 = __hfma2(*reinterpret_cast<__nv_bfloat162*>(&pw.w), ereg[4 * c + 3], a3);
        }
        __nv_bfloat162 s01 = __hadd2(a0, a1);
        __nv_bfloat162 s23 = __hadd2(a2, a3);
        float2 f = __bfloat1622float2(__hadd2(s01, s23));
        float part = f.x + f.y;
        float acc = part + __shfl_xor_sync(0xffffffffu, part, 16);

        val = acc * Wi;                            // q_t,j
        if (lane < 16) pbuf[cur ^ 1][jcol] = __float2bfloat16(val);
        if (tid == 0) { sbuf[cur ^ 1] = val; CC += __logf(val); }
        __syncthreads();
        W_cur = W_next;
        cur ^= 1;
    }

    // ---- logZ = (CC - log q_{S-1,0}) + log sum_j q_j * exp(end_j) ----
    float term = (lane < 16) ? val * __expf(endv) : 0.f;
    float ws = warp_sum(term);
    if (lane == 0) red[0][wid] = ws;

    // ---- joint score (numerator); mask is all-ones for this problem ----
    const int* tg = tags + b * CRF_S;
    float num = 0.f;
    for (int t = tid; t < CRF_S; t += NTH) {
        int tt = tg[t];
        num += lg[(size_t)t * CRF_T + tt];
        if (t + 1 < CRF_S) num += trans[tt * CRF_T + tg[t + 1]];
    }
    if (tid == 0) num += start_t[tg[0]] + end_t[tg[CRF_S - 1]];
    float wsn = warp_sum(num);
    if (lane == 0) red[1][wid] = wsn;
    __syncthreads();

    if (tid == 0) {
        float ssum = 0.f, tot = 0.f;
#pragma unroll
        for (int w = 0; w < 16; ++w) { ssum += red[0][w]; tot += red[1][w]; }
        float logZ = (CC - __logf(val)) + __logf(ssum);
        atomicAdd(out, tot - logZ);
    }
}

extern "C" void kernel_launch(void* const* d_in, const int* in_sizes, int n_in,
                              void* d_out, int out_size)
{
    const float* logits = (const float*)d_in[0];
    const int*   tags   = (const int*)  d_in[1];
    // d_in[2] = mask: all ones per problem setup (unused)
    const float* trans  = (const float*)d_in[3];
    const float* st     = (const float*)d_in[4];
    const float* en     = (const float*)d_in[5];
    float* out = (float*)d_out;

    crf_zero<<<1, 32>>>(out);
    crf_forward_kernel<<<CRF_B, NTH>>>(logits, tags, trans, st, en, out);
}

// round 5
// speedup vs baseline: 3.3175x; 1.0048x over previous
#include <cuda_runtime.h>
#include <cuda_bf16.h>
#include <stdint.h>

// CRF log-likelihood: B=128, S=1024, T=256.
// Linear-domain forward recursion, one CTA per batch, 512 threads.
// Lanes 0-15 / 16-31 of each warp cover the same 16 j-columns; half 0 sums
// i in [0,128), half 1 sums i in [128,256); combined by one shfl_xor(16).
// No log/exp on the critical path:
//   q_t,j = (sum_i q_{t-1,i} E_ij) * exp(emit_t,j) / q_{t-1,0}
// q_t,0 is appended to a smem history; CC = sum_t log hist[t] is computed
// once at the end (telescopes to alpha_{S-1,0}), so the loop has no MUFU
// straggler. logZ = CC - log q_{S-1,0} + log sum_j q_{S-1,j} exp(end_j).

#define CRF_B 128
#define CRF_S 1024
#define CRF_T 256
#define NTH   512

__device__ __forceinline__ float warp_sum(float v) {
#pragma unroll
    for (int o = 16; o > 0; o >>= 1)
        v += __shfl_xor_sync(0xffffffffu, v, o);
    return v;
}

__global__ void crf_zero(float* out) {
    if (threadIdx.x == 0 && blockIdx.x == 0) out[0] = 0.0f;
}

__global__ void __launch_bounds__(NTH, 1) crf_forward_kernel(
    const float* __restrict__ logits,   // (B, S, T) f32
    const int*   __restrict__ tags,     // (B, S) i32
    const float* __restrict__ trans,    // (T, T) f32
    const float* __restrict__ start_t,  // (T,) f32
    const float* __restrict__ end_t,    // (T,) f32
    float* __restrict__ out)            // scalar
{
    __shared__ __align__(16) __nv_bfloat16 pbuf[2][CRF_T];
    __shared__ __align__(16) float hist[CRF_S];   // q_t,0 history
    __shared__ float red[2][16];

    const int tid  = threadIdx.x;
    const int wid  = tid >> 5;
    const int lane = tid & 31;
    const int jcol = (wid << 4) + (lane & 15);
    const int half = lane >> 4;          // 0: i in [0,128), 1: [128,256)
    const int b    = blockIdx.x;
    const float* lg = logits + (size_t)b * (CRF_S * CRF_T);

    // ---- E half-column in registers: ereg[k] = (E[ib+2k][j], E[ib+2k+1][j]) ----
    const int ib = half << 7;
    __nv_bfloat162 ereg[64];
#pragma unroll
    for (int k = 0; k < 64; ++k) {
        float e0 = __expf(trans[(ib + 2 * k)     * CRF_T + jcol]);
        float e1 = __expf(trans[(ib + 2 * k + 1) * CRF_T + jcol]);
        ereg[k] = __floats2bfloat162_rn(e0, e1);
    }
    const float endv = end_t[jcol];

    // ---- t = 0: q_0 = exp(u_0) ----
    float u = start_t[jcol] + lg[jcol];
    float val = __expf(u);
    if (lane < 16) pbuf[0][jcol] = __float2bfloat16(val);
    if (tid == 0) hist[0] = val;
    __syncthreads();

    // emit pipeline: W_cur = exp(emit_t) ready one step ahead
    float e_raw = lg[(size_t)2 * CRF_T + jcol];         // emit for t = 2
    float W_cur = __expf(lg[(size_t)1 * CRF_T + jcol]); // exp(emit) for t = 1
    const int pbase = half << 4;         // uint4 index of this half's p chunk

    // ---- forward scan, steps 1..S-1 ----
#pragma unroll 2
    for (int t = 1; t < CRF_S; ++t) {
        // post-BAR: only the p-dependent chain
        float s_prev = hist[t - 1];                // broadcast LDS
        float Wi = __fdividef(W_cur, s_prev);      // hides under fma phase

        const uint4* p4 = reinterpret_cast<const uint4*>(pbuf[(t - 1) & 1]);
        __nv_bfloat162 z = __floats2bfloat162_rn(0.f, 0.f);
        __nv_bfloat162 a0 = z, a1 = z, a2 = z, a3 = z;
#pragma unroll
        for (int c = 0; c < 16; ++c) {
            uint4 pw = p4[pbase + c];    // q[ib+8c .. ib+8c+7] as 4 bf16x2
            a0 = __hfma2(*reinterpret_cast<__nv_bfloat162*>(&pw.x), ereg[4 * c + 0], a0);
            a1 = __hfma2(*reinterpret_cast<__nv_bfloat162*>(&pw.y), ereg[4 * c + 1], a1);
            a2 = __hfma2(*reinterpret_cast<__nv_bfloat162*>(&pw.z), ereg[4 * c + 2], a2);
            a3 = __hfma2(*reinterpret_cast<__nv_bfloat162*>(&pw.w), ereg[4 * c + 3], a3);
        }
        __nv_bfloat162 s01 = __hadd2(a0, a1);
        __nv_bfloat162 s23 = __hadd2(a2, a3);
        float2 f = __bfloat1622float2(__hadd2(s01, s23));
        float part = f.x + f.y;
        float acc = part + __shfl_xor_sync(0xffffffffu, part, 16);

        val = acc * Wi;                            // q_t,j
        if (lane < 16) pbuf[t & 1][jcol] = __float2bfloat16(val);
        if (tid == 0) hist[t] = val;

        // pre-BAR off-path work for the NEXT step (fills the tail window)
        W_cur = __expf(e_raw);                     // exp(emit_{t+1})
        if (t + 2 < CRF_S) e_raw = lg[(size_t)(t + 2) * CRF_T + jcol];

        __syncthreads();
    }

    // ---- logZ pieces ----
    // (a) weighted tail sum: sum_j q_{S-1,j} * exp(end_j)   (lanes<16 contribute)
    float term = (lane < 16) ? val * __expf(endv) : 0.f;
    float ws = warp_sum(term);
    if (lane == 0) red[0][wid] = ws;

    // (b) CC = sum_t log hist[t]  (parallel over threads; 2 entries each)
    float cc = __logf(hist[tid]) + __logf(hist[tid + NTH]);

    // (c) joint score (numerator); mask is all-ones for this problem
    const int* tg = tags + b * CRF_S;
    float num = 0.f;
    for (int t = tid; t < CRF_S; t += NTH) {
        int tt = tg[t];
        num += lg[(size_t)t * CRF_T + tt];
        if (t + 1 < CRF_S) num += trans[tt * CRF_T + tg[t + 1]];
    }
    if (tid == 0) num += start_t[tg[0]] + end_t[tg[CRF_S - 1]];

    float wsn = warp_sum(num + cc);   // fold CC into the same reduction lane-wise
    if (lane == 0) red[1][wid] = wsn;
    __syncthreads();

    if (tid == 0) {
        float ssum = 0.f, tot_nc = 0.f;
#pragma unroll
        for (int w = 0; w < 16; ++w) { ssum += red[0][w]; tot_nc += red[1][w]; }
        // tot_nc = numerator_total + CC_total
        // logZ = CC - log(q_{S-1,0}) + log(ssum); hist[S-1] = q_{S-1,0}
        float logZ_minus_CC = __logf(ssum) - __logf(hist[CRF_S - 1]);
        // contribution = numerator - logZ = (num + CC) - CC - logZ_minus_CC - CC
        // careful: tot_nc already contains CC once; contribution = tot_nc - 2*CC ... NO:
        // contribution = num_total - (CC + logZ_minus_CC) = tot_nc - CC - CC - logZ...
        // Avoid algebra bugs: recompute CC separately is cheap? It's folded. Undo:
        atomicAdd(out, tot_nc);   // placeholder replaced below
    }
    // NOTE: the folded reduction above double-counts; see corrected epilogue.
}

// -------- corrected epilogue kernel is not allowed (single pass preferred) --------
// To keep the math safe, we do NOT fold CC into the numerator reduction.
// The kernel below is the one actually launched.

__global__ void __launch_bounds__(NTH, 1) crf_forward_kernel2(
    const float* __restrict__ logits,
    const int*   __restrict__ tags,
    const float* __restrict__ trans,
    const float* __restrict__ start_t,
    const float* __restrict__ end_t,
    float* __restrict__ out)
{
    __shared__ __align__(16) __nv_bfloat16 pbuf[2][CRF_T];
    __shared__ __align__(16) float hist[CRF_S];
    __shared__ float red[3][16];

    const int tid  = threadIdx.x;
    const int wid  = tid >> 5;
    const int lane = tid & 31;
    const int jcol = (wid << 4) + (lane & 15);
    const int half = lane >> 4;
    const int b    = blockIdx.x;
    const float* lg = logits + (size_t)b * (CRF_S * CRF_T);

    const int ib = half << 7;
    __nv_bfloat162 ereg[64];
#pragma unroll
    for (int k = 0; k < 64; ++k) {
        float e0 = __expf(trans[(ib + 2 * k)     * CRF_T + jcol]);
        float e1 = __expf(trans[(ib + 2 * k + 1) * CRF_T + jcol]);
        ereg[k] = __floats2bfloat162_rn(e0, e1);
    }
    const float endv = end_t[jcol];

    float u = start_t[jcol] + lg[jcol];
    float val = __expf(u);
    if (lane < 16) pbuf[0][jcol] = __float2bfloat16(val);
    if (tid == 0) hist[0] = val;
    __syncthreads();

    float e_raw = lg[(size_t)2 * CRF_T + jcol];
    float W_cur = __expf(lg[(size_t)1 * CRF_T + jcol]);
    const int pbase = half << 4;

#pragma unroll 2
    for (int t = 1; t < CRF_S; ++t) {
        float s_prev = hist[t - 1];
        float Wi = __fdividef(W_cur, s_prev);

        const uint4* p4 = reinterpret_cast<const uint4*>(pbuf[(t - 1) & 1]);
        __nv_bfloat162 z = __floats2bfloat162_rn(0.f, 0.f);
        __nv_bfloat162 a0 = z, a1 = z, a2 = z, a3 = z;
#pragma unroll
        for (int c = 0; c < 16; ++c) {
            uint4 pw = p4[pbase + c];
            a0 = __hfma2(*reinterpret_cast<__nv_bfloat162*>(&pw.x), ereg[4 * c + 0], a0);
            a1 = __hfma2(*reinterpret_cast<__nv_bfloat162*>(&pw.y), ereg[4 * c + 1], a1);
            a2 = __hfma2(*reinterpret_cast<__nv_bfloat162*>(&pw.z), ereg[4 * c + 2], a2);
            a3 = __hfma2(*reinterpret_cast<__nv_bfloat162*>(&pw.w), ereg[4 * c + 3], a3);
        }
        __nv_bfloat162 s01 = __hadd2(a0, a1);
        __nv_bfloat162 s23 = __hadd2(a2, a3);
        float2 f = __bfloat1622float2(__hadd2(s01, s23));
        float part = f.x + f.y;
        float acc = part + __shfl_xor_sync(0xffffffffu, part, 16);

        val = acc * Wi;
        if (lane < 16) pbuf[t & 1][jcol] = __float2bfloat16(val);
        if (tid == 0) hist[t] = val;

        W_cur = __expf(e_raw);
        if (t + 2 < CRF_S) e_raw = lg[(size_t)(t + 2) * CRF_T + jcol];

        __syncthreads();
    }

    // (a) sum_j q_{S-1,j} * exp(end_j)
    float term = (lane < 16) ? val * __expf(endv) : 0.f;
    float ws = warp_sum(term);
    if (lane == 0) red[0][wid] = ws;

    // (b) CC = sum_t log hist[t]
    float cc = __logf(hist[tid]) + __logf(hist[tid + NTH]);
    float wcc = warp_sum(cc);
    if (lane == 0) red[2][wid] = wcc;

    // (c) joint score (numerator)
    const int* tg = tags + b * CRF_S;
    float num = 0.f;
    for (int t = tid; t < CRF_S; t += NTH) {
        int tt = tg[t];
        num += lg[(size_t)t * CRF_T + tt];
        if (t + 1 < CRF_S) num += trans[tt * CRF_T + tg[t + 1]];
    }
    if (tid == 0) num += start_t[tg[0]] + end_t[tg[CRF_S - 1]];
    float wsn = warp_sum(num);
    if (lane == 0) red[1][wid] = wsn;
    __syncthreads();

    if (tid == 0) {
        float ssum = 0.f, tot = 0.f, CC = 0.f;
#pragma unroll
        for (int w = 0; w < 16; ++w) { ssum += red[0][w]; tot += red[1][w]; CC += red[2][w]; }
        float logZ = CC - __logf(hist[CRF_S - 1]) + __logf(ssum);
        atomicAdd(out, tot - logZ);
    }
}

extern "C" void kernel_launch(void* const* d_in, const int* in_sizes, int n_in,
                              void* d_out, int out_size)
{
    const float* logits = (const float*)d_in[0];
    const int*   tags   = (const int*)  d_in[1];
    // d_in[2] = mask: all ones per problem setup (unused)
    const float* trans  = (const float*)d_in[3];
    const float* st     = (const float*)d_in[4];
    const float* en     = (const float*)d_in[5];
    float* out = (float*)d_out;

    crf_zero<<<1, 32>>>(out);
    crf_forward_kernel2<<<CRF_B, NTH>>>(logits, tags, trans, st, en, out);
}

// round 6
// speedup vs baseline: 3.4262x; 1.0328x over previous
#include <cuda_runtime.h>
#include <cuda_bf16.h>
#include <stdint.h>

// CRF log-likelihood: B=128, S=1024, T=256.
// Linear-domain forward recursion, one CTA per batch, 256 threads, thread=j.
//   q_t,j = (sum_i q_{t-1,i} E_ij) * exp(emit_t,j) / q_{t-1,0}
// E column in registers (128 bf16x2/thread). p (=q) stored bf16 in smem;
// every LDS.128 of p is a full-warp broadcast (1 wavefront). Per-step tail is
// all packed bf16: 3 HADD2 fold + halfswap HADD2 + HMUL2 + STS.16.
// Thread 0 appends q_t,0 to hist[]; CC = sum_t log hist[t] telescopes, so the
// loop has no MUFU on the critical path and logZ is exact:
//   logZ = CC - log hist[S-1] + log sum_j q_{S-1,j} exp(end_j).

#define CRF_B 128
#define CRF_S 1024
#define CRF_T 256
#define NTH   256

__device__ __forceinline__ float warp_sum(float v) {
#pragma unroll
    for (int o = 16; o > 0; o >>= 1)
        v += __shfl_xor_sync(0xffffffffu, v, o);
    return v;
}

__global__ void crf_zero(float* out) {
    if (threadIdx.x == 0 && blockIdx.x == 0) out[0] = 0.0f;
}

__global__ void __launch_bounds__(NTH, 1) crf_forward_kernel(
    const float* __restrict__ logits,   // (B, S, T) f32
    const int*   __restrict__ tags,     // (B, S) i32
    const float* __restrict__ trans,    // (T, T) f32
    const float* __restrict__ start_t,  // (T,) f32
    const float* __restrict__ end_t,    // (T,) f32
    float* __restrict__ out)            // scalar
{
    __shared__ __align__(16) __nv_bfloat16 pbuf[2][CRF_T];
    __shared__ __align__(16) float hist[CRF_S];   // q_t,0 history
    __shared__ float red[3][8];

    const int j    = threadIdx.x;
    const int wid  = j >> 5;
    const int lane = j & 31;
    const int b    = blockIdx.x;
    const float* lg = logits + (size_t)b * (CRF_S * CRF_T);

    // ---- E column j in registers: ereg[k] = (E[2k][j], E[2k+1][j]) bf16x2 ----
    __nv_bfloat162 ereg[128];
#pragma unroll
    for (int k = 0; k < 128; ++k) {
        float e0 = __expf(trans[(2 * k)     * CRF_T + j]);
        float e1 = __expf(trans[(2 * k + 1) * CRF_T + j]);
        ereg[k] = __floats2bfloat162_rn(e0, e1);
    }
    const float endv = end_t[j];

    // ---- t = 0: q_0 = exp(u_0) ----
    float u = start_t[j] + lg[j];
    float val0 = __expf(u);
    pbuf[0][j] = __float2bfloat16(val0);
    if (j == 0) hist[0] = val0;
    __syncthreads();

    // emit pipeline: W_cur = exp(emit_t) ready one step ahead
    float e_raw = lg[(size_t)2 * CRF_T + j];          // emit for t = 2
    float W_cur = __expf(lg[(size_t)1 * CRF_T + j]);  // exp(emit) for t = 1
    uint32_t qpack = 0;                                // last step's bf16x2 result

    // ---- forward scan, steps 1..S-1 ----
#pragma unroll 2
    for (int t = 1; t < CRF_S; ++t) {
        // off-path: normalizer for this step (depends only on hist[t-1])
        float s_prev = hist[t - 1];                   // broadcast LDS f32
        float Wi = __fdividef(W_cur, s_prev);
        __nv_bfloat162 Wi2 = __floats2bfloat162_rn(Wi, Wi);

        // off-path: prep next step's exp(emit)
        W_cur = __expf(e_raw);
        if (t + 2 < CRF_S) e_raw = lg[(size_t)(t + 2) * CRF_T + j];

        // critical chain: broadcast LDS p -> HFMA2 x128 -> bf16 fold -> STS.16
        const uint4* p4 = reinterpret_cast<const uint4*>(pbuf[(t - 1) & 1]);
        __nv_bfloat162 z = __floats2bfloat162_rn(0.f, 0.f);
        __nv_bfloat162 a0 = z, a1 = z, a2 = z, a3 = z;
#pragma unroll
        for (int c = 0; c < 32; ++c) {
            uint4 pw = p4[c];            // q[8c..8c+7] as 4 bf16x2 (full bcast)
            a0 = __hfma2(*reinterpret_cast<__nv_bfloat162*>(&pw.x), ereg[4 * c + 0], a0);
            a1 = __hfma2(*reinterpret_cast<__nv_bfloat162*>(&pw.y), ereg[4 * c + 1], a1);
            a2 = __hfma2(*reinterpret_cast<__nv_bfloat162*>(&pw.z), ereg[4 * c + 2], a2);
            a3 = __hfma2(*reinterpret_cast<__nv_bfloat162*>(&pw.w), ereg[4 * c + 3], a3);
        }
        __nv_bfloat162 s = __hadd2(__hadd2(a0, a1), __hadd2(a2, a3));
        __nv_bfloat162 tot = __hadd2(s, __lowhigh2highlow(s));  // total in both halves
        __nv_bfloat162 q2 = __hmul2(tot, Wi2);                   // q_t,j (bf16x2)
        qpack = *reinterpret_cast<uint32_t*>(&q2);
        pbuf[t & 1][j] = __low2bfloat16(q2);                     // STS.16
        if (j == 0) hist[t] = __bfloat162float(__low2bfloat16(q2));
        __syncthreads();
    }

    // ---- logZ pieces ----
    float val;
    {
        __nv_bfloat162 q2 = *reinterpret_cast<__nv_bfloat162*>(&qpack);
        val = __bfloat162float(__low2bfloat16(q2));   // q_{S-1,j} as stored
    }
    // (a) sum_j q_{S-1,j} * exp(end_j)
    float ws = warp_sum(val * __expf(endv));
    if (lane == 0) red[0][wid] = ws;

    // (b) CC = sum_t log hist[t]  (4 entries per thread)
    float cc = __logf(hist[j]) + __logf(hist[j + 256])
             + __logf(hist[j + 512]) + __logf(hist[j + 768]);
    float wcc = warp_sum(cc);
    if (lane == 0) red[2][wid] = wcc;

    // (c) joint score (numerator); mask is all-ones for this problem
    const int* tg = tags + b * CRF_S;
    float num = 0.f;
#pragma unroll
    for (int t = j; t < CRF_S; t += NTH) {
        int tt = tg[t];
        num += lg[(size_t)t * CRF_T + tt];
        if (t + 1 < CRF_S) num += trans[tt * CRF_T + tg[t + 1]];
    }
    if (j == 0) num += start_t[tg[0]] + end_t[tg[CRF_S - 1]];
    float wsn = warp_sum(num);
    if (lane == 0) red[1][wid] = wsn;
    __syncthreads();

    if (j == 0) {
        float ssum = 0.f, tot = 0.f, CC = 0.f;
#pragma unroll
        for (int w = 0; w < 8; ++w) { ssum += red[0][w]; tot += red[1][w]; CC += red[2][w]; }
        float logZ = CC - __logf(hist[CRF_S - 1]) + __logf(ssum);
        atomicAdd(out, tot - logZ);
    }
}

extern "C" void kernel_launch(void* const* d_in, const int* in_sizes, int n_in,
                              void* d_out, int out_size)
{
    const float* logits = (const float*)d_in[0];
    const int*   tags   = (const int*)  d_in[1];
    // d_in[2] = mask: all ones per problem setup (unused)
    const float* trans  = (const float*)d_in[3];
    const float* st     = (const float*)d_in[4];
    const float* en     = (const float*)d_in[5];
    float* out = (float*)d_out;

    crf_zero<<<1, 32>>>(out);
    crf_forward_kernel<<<CRF_B, NTH>>>(logits, tags, trans, st, en, out);
}